// round 7
// baseline (speedup 1.0000x reference)
#include <cuda_runtime.h>
#include <cuda_bf16.h>

// Problem constants
#define BB   8
#define NN   1024
#define HH   256
#define WW   256
#define CC   256
#define HID  512
#define MTOT (BB * NN)        // 8192 rows

// Ping-pong activation buffers (static device scratch; no allocation).
__device__ float g_bufA[MTOT * HID];
__device__ float g_bufB[MTOT * HID];

// ---------------------------------------------------------------------------
// Kernel 1: bilinear sampling -> h0 [B, N, 256]
// grid = B*N blocks, 256 threads (one per channel)
// ---------------------------------------------------------------------------
__global__ __launch_bounds__(256)
void sample_kernel(const float* __restrict__ vertices,
                   const float* __restrict__ features,
                   float* __restrict__ out)
{
    const int p = blockIdx.x;            // b*N + n
    const int b = p >> 10;               // N = 1024
    const int c = threadIdx.x;

    const float y = vertices[p * 2 + 0];
    const float x = vertices[p * 2 + 1];
    const float y0f = floorf(y), x0f = floorf(x);
    const int y0 = (int)y0f, x0 = (int)x0f;
    const float wy1 = y - y0f, wx1 = x - x0f;
    const float wy0 = 1.0f - wy1, wx0 = 1.0f - wx1;

    const float* fb = features + (size_t)b * HH * WW * CC;

    float acc = 0.0f;
    {
        int yi = y0, xi = x0;
        if (yi >= 0 && yi < HH && xi >= 0 && xi < WW)
            acc += fb[(yi * WW + xi) * CC + c] * (wy0 * wx0);
    }
    {
        int yi = y0, xi = x0 + 1;
        if (yi >= 0 && yi < HH && xi >= 0 && xi < WW)
            acc += fb[(yi * WW + xi) * CC + c] * (wy0 * wx1);
    }
    {
        int yi = y0 + 1, xi = x0;
        if (yi >= 0 && yi < HH && xi >= 0 && xi < WW)
            acc += fb[(yi * WW + xi) * CC + c] * (wy1 * wx0);
    }
    {
        int yi = y0 + 1, xi = x0 + 1;
        if (yi >= 0 && yi < HH && xi >= 0 && xi < WW)
            acc += fb[(yi * WW + xi) * CC + c] * (wy1 * wx1);
    }

    out[p * CC + c] = acc;
}

// ---------------------------------------------------------------------------
// Kernel 2: dilated Conv1D (K=3, SAME) + bias + ReLU as implicit GEMM.
//   out[m, co] = relu(bias[co] + sum_{kk} A[m,kk] * W[kk, co])
//   A[m, kk]: kk = tap*CIN + ci ; value = in[b, n+(tap-1)*rate, ci] (0 if OOB)
//   W is w[3, CIN, 512] viewed as [3*CIN, 512] row-major (native layout).
// Tiling: BM=128, BN=128, BK=8, 256 threads, 8x8 micro-tile.
// Double-buffered smem pipeline: prefetch next K-tile during compute,
// ONE __syncthreads per K-step.
// grid = (MTOT/128, 512/128)
// ---------------------------------------------------------------------------
template <int CIN>
__global__ __launch_bounds__(256, 2)
void conv1d_gemm(const float* __restrict__ in,   // [MTOT, CIN]
                 const float* __restrict__ w,    // [3*CIN, 512]
                 const float* __restrict__ bias, // [512]
                 float* __restrict__ out,        // [MTOT, 512]
                 int rate)
{
    constexpr int KK = 3 * CIN;
    constexpr int NT = KK / 8;       // number of K-tiles
    __shared__ float As[2][8][128];  // [buf][k][row]  (transposed on store)
    __shared__ float Bs[2][8][128];  // [buf][k][col]

    const int tid = threadIdx.x;
    const int m0  = blockIdx.x * 128;
    const int co0 = blockIdx.y * 128;
    const int tx = tid & 15;       // 0..15 -> 8 output cols each
    const int ty = tid >> 4;       // 0..15 -> 8 output rows each

    // A-tile load mapping: 128 rows x 8 kk, one float4 per thread
    const int a_row = tid >> 1;            // 0..127
    const int a_c4  = (tid & 1) * 4;       // 0 or 4
    const int rowg  = m0 + a_row;          // global row (b*1024 + n)
    const int n     = rowg & (NN - 1);
    const int brow  = (rowg >> 10) * NN;   // b * 1024

    // B-tile load mapping: 8 kk x 128 cols, one float4 per thread
    const int b_row = tid >> 5;            // 0..7
    const int b_c4  = (tid & 31) << 2;     // 0..124

    float acc[8][8];
#pragma unroll
    for (int i = 0; i < 8; ++i)
#pragma unroll
        for (int j = 0; j < 8; ++j) acc[i][j] = 0.0f;

    // ---- tile loaders (global -> registers) ----
    auto load_a = [&](int kk0) -> float4 {
        const int tap = kk0 / CIN;                 // CIN is pow2
        const int ci  = (kk0 & (CIN - 1)) + a_c4;
        const int np  = n + (tap - 1) * rate;
        float4 av = make_float4(0.f, 0.f, 0.f, 0.f);
        if ((unsigned)np < (unsigned)NN)
            av = *reinterpret_cast<const float4*>(in + (size_t)(brow + np) * CIN + ci);
        return av;
    };
    auto load_b = [&](int kk0) -> float4 {
        return *reinterpret_cast<const float4*>(w + (size_t)(kk0 + b_row) * HID + co0 + b_c4);
    };
    auto store_a = [&](int buf, float4 av) {
        As[buf][a_c4 + 0][a_row] = av.x;
        As[buf][a_c4 + 1][a_row] = av.y;
        As[buf][a_c4 + 2][a_row] = av.z;
        As[buf][a_c4 + 3][a_row] = av.w;
    };
    auto store_b = [&](int buf, float4 bv) {
        *reinterpret_cast<float4*>(&Bs[buf][b_row][b_c4]) = bv;
    };

    // ---- prologue: tile 0 -> smem[0] ----
    store_a(0, load_a(0));
    store_b(0, load_b(0));
    __syncthreads();

    for (int t = 0; t < NT; ++t) {
        const int cur = t & 1;

        // prefetch next tile into registers (overlaps with FFMA below)
        float4 a_next, b_next;
        if (t + 1 < NT) {
            a_next = load_a((t + 1) * 8);
            b_next = load_b((t + 1) * 8);
        }

        // compute on current tile
#pragma unroll
        for (int k = 0; k < 8; ++k) {
            float4 a0 = *reinterpret_cast<const float4*>(&As[cur][k][ty * 8]);
            float4 a1 = *reinterpret_cast<const float4*>(&As[cur][k][ty * 8 + 4]);
            float4 b0 = *reinterpret_cast<const float4*>(&Bs[cur][k][tx * 8]);
            float4 b1 = *reinterpret_cast<const float4*>(&Bs[cur][k][tx * 8 + 4]);
            float ar[8] = {a0.x, a0.y, a0.z, a0.w, a1.x, a1.y, a1.z, a1.w};
            float br[8] = {b0.x, b0.y, b0.z, b0.w, b1.x, b1.y, b1.z, b1.w};
#pragma unroll
            for (int i = 0; i < 8; ++i)
#pragma unroll
                for (int j = 0; j < 8; ++j)
                    acc[i][j] = fmaf(ar[i], br[j], acc[i][j]);
        }

        // write prefetched tile into the other buffer, then barrier
        if (t + 1 < NT) {
            store_a(cur ^ 1, a_next);
            store_b(cur ^ 1, b_next);
        }
        __syncthreads();
    }

    // ---- epilogue: bias + relu, float4 stores ----
    float bv[8];
#pragma unroll
    for (int j = 0; j < 8; ++j) bv[j] = bias[co0 + tx * 8 + j];

#pragma unroll
    for (int i = 0; i < 8; ++i) {
        const int row = m0 + ty * 8 + i;
        float* op = out + (size_t)row * HID + co0 + tx * 8;
        float4 v0, v1;
        v0.x = fmaxf(acc[i][0] + bv[0], 0.f);
        v0.y = fmaxf(acc[i][1] + bv[1], 0.f);
        v0.z = fmaxf(acc[i][2] + bv[2], 0.f);
        v0.w = fmaxf(acc[i][3] + bv[3], 0.f);
        v1.x = fmaxf(acc[i][4] + bv[4], 0.f);
        v1.y = fmaxf(acc[i][5] + bv[5], 0.f);
        v1.z = fmaxf(acc[i][6] + bv[6], 0.f);
        v1.w = fmaxf(acc[i][7] + bv[7], 0.f);
        *reinterpret_cast<float4*>(op)     = v0;
        *reinterpret_cast<float4*>(op + 4) = v1;
    }
}

// ---------------------------------------------------------------------------
// Kernel 3: offset head (1x1 conv, no bias) + add vertices.
// One warp per point; grid = MTOT/8 blocks x 256 threads.
// ---------------------------------------------------------------------------
__global__ __launch_bounds__(256)
void offset_head(const float* __restrict__ h,      // [MTOT, 512]
                 const float* __restrict__ w_off,  // [512, 2]
                 const float* __restrict__ vertices,
                 float* __restrict__ out)          // [MTOT, 2]
{
    const int warp = threadIdx.x >> 5;
    const int lane = threadIdx.x & 31;
    const int p = blockIdx.x * 8 + warp;
    if (p >= MTOT) return;

    const float* hp = h + (size_t)p * HID;
    float s0 = 0.f, s1 = 0.f;
#pragma unroll
    for (int ci = lane; ci < HID; ci += 32) {
        float v = hp[ci];
        s0 = fmaf(v, w_off[2 * ci + 0], s0);
        s1 = fmaf(v, w_off[2 * ci + 1], s1);
    }
#pragma unroll
    for (int o = 16; o > 0; o >>= 1) {
        s0 += __shfl_xor_sync(0xFFFFFFFFu, s0, o);
        s1 += __shfl_xor_sync(0xFFFFFFFFu, s1, o);
    }
    if (lane == 0) {
        out[2 * p + 0] = vertices[2 * p + 0] + s0;
        out[2 * p + 1] = vertices[2 * p + 1] + s1;
    }
}

// ---------------------------------------------------------------------------
// Launch
// Inputs (metadata order): vertices, features, w0,b0, w1,b1, ..., w5,b5, w_off
// ---------------------------------------------------------------------------
extern "C" void kernel_launch(void* const* d_in, const int* in_sizes, int n_in,
                              void* d_out, int out_size)
{
    const float* vertices = (const float*)d_in[0];
    const float* features = (const float*)d_in[1];
    const float* w[6];
    const float* b[6];
    for (int i = 0; i < 6; ++i) {
        w[i] = (const float*)d_in[2 + 2 * i];
        b[i] = (const float*)d_in[3 + 2 * i];
    }
    const float* w_off = (const float*)d_in[14];
    float* out = (float*)d_out;

    float *pA, *pB;
    cudaGetSymbolAddress((void**)&pA, g_bufA);
    cudaGetSymbolAddress((void**)&pB, g_bufB);

    // 1) bilinear sample -> pA [MTOT, 256]
    sample_kernel<<<MTOT, 256>>>(vertices, features, pA);

    const dim3 grid(MTOT / 128, HID / 128);

    // 2) conv stack, rates (1,3,9,9,3,1), ping-pong A<->B
    conv1d_gemm<256><<<grid, 256>>>(pA, w[0], b[0], pB, 1);
    conv1d_gemm<512><<<grid, 256>>>(pB, w[1], b[1], pA, 3);
    conv1d_gemm<512><<<grid, 256>>>(pA, w[2], b[2], pB, 9);
    conv1d_gemm<512><<<grid, 256>>>(pB, w[3], b[3], pA, 9);
    conv1d_gemm<512><<<grid, 256>>>(pA, w[4], b[4], pB, 3);
    conv1d_gemm<512><<<grid, 256>>>(pB, w[5], b[5], pA, 1);

    // 3) offset head + residual add -> d_out [MTOT, 2]
    offset_head<<<MTOT / 8, 256>>>(pA, w_off, vertices, out);
}

// round 15
// speedup vs baseline: 2.2980x; 2.2980x over previous
#include <cuda_runtime.h>
#include <cuda_bf16.h>
#include <cstdint>

// ---------------------------------------------------------------------------
// Problem constants
// ---------------------------------------------------------------------------
#define BB   8
#define NN   1024
#define HH   256
#define WW   256
#define CC   256
#define HID  512
#define MTOT (BB * NN)        // 8192 rows

// ---------------------------------------------------------------------------
// Static device scratch (no allocation allowed)
// ---------------------------------------------------------------------------
__device__ __nv_bfloat16 g_h0_hi[MTOT * CC];
__device__ __nv_bfloat16 g_h0_lo[MTOT * CC];
__device__ __nv_bfloat16 g_a_hi[MTOT * HID];
__device__ __nv_bfloat16 g_a_lo[MTOT * HID];
__device__ __nv_bfloat16 g_b_hi[MTOT * HID];
__device__ __nv_bfloat16 g_b_lo[MTOT * HID];
// transposed weights: layer0 [512 x 768], layers1-5 [512 x 1536]
#define WT0_SZ   (512 * 768)
#define WTI_SZ   (512 * 1536)
#define WT_TOTAL (WT0_SZ + 5 * WTI_SZ)
__device__ __nv_bfloat16 g_wt_hi[WT_TOTAL];
__device__ __nv_bfloat16 g_wt_lo[WT_TOTAL];

// ---------------------------------------------------------------------------
// Helpers (base-ISA only: ldmatrix + mma.sync, both legal on sm_103 generic)
// ---------------------------------------------------------------------------
__device__ __forceinline__ uint32_t smem_u32(const void* p) {
    uint32_t a;
    asm("{ .reg .u64 t; cvta.to.shared.u64 t, %1; cvt.u32.u64 %0, t; }" : "=r"(a) : "l"(p));
    return a;
}

#define LDMX4(r0, r1, r2, r3, addr) \
    asm volatile("ldmatrix.sync.aligned.m8n8.x4.shared.b16 {%0,%1,%2,%3}, [%4];" \
                 : "=r"(r0), "=r"(r1), "=r"(r2), "=r"(r3) : "r"(addr))

#define MMA16816(d, a, b) \
    asm volatile("mma.sync.aligned.m16n8k16.row.col.f32.bf16.bf16.f32 " \
                 "{%0,%1,%2,%3}, {%4,%5,%6,%7}, {%8,%9}, {%0,%1,%2,%3};" \
                 : "+f"((d)[0]), "+f"((d)[1]), "+f"((d)[2]), "+f"((d)[3]) \
                 : "r"((a)[0]), "r"((a)[1]), "r"((a)[2]), "r"((a)[3]), \
                   "r"((b)[0]), "r"((b)[1]))

// ---------------------------------------------------------------------------
// SMEM layout for conv_mma (dynamic, bytes)
//   two buffers of 40960: [Ah 10240 | Al 10240 | Bh 10240 | Bl 10240]
//   each array: 128 rows x 40 halves (32 data + 8 pad) = 80 B/row
//   bias: 128 floats at 81920
// ---------------------------------------------------------------------------
#define BUFB     40960
#define ROWB     80
#define OFF_AL   10240
#define OFF_BH   20480
#define OFF_BL   30720
#define OFF_BIAS 81920
#define SMEM_TOTAL 82432

// ---------------------------------------------------------------------------
// Kernel 1: bilinear sampling -> h0 hi/lo bf16 [MTOT, 256]
// ---------------------------------------------------------------------------
__global__ __launch_bounds__(256)
void sample_kernel(const float* __restrict__ vertices,
                   const float* __restrict__ features,
                   __nv_bfloat16* __restrict__ out_hi,
                   __nv_bfloat16* __restrict__ out_lo)
{
    const int p = blockIdx.x;
    const int b = p >> 10;
    const int c = threadIdx.x;

    const float y = vertices[p * 2 + 0];
    const float x = vertices[p * 2 + 1];
    const float y0f = floorf(y), x0f = floorf(x);
    const int y0 = (int)y0f, x0 = (int)x0f;
    const float wy1 = y - y0f, wx1 = x - x0f;
    const float wy0 = 1.0f - wy1, wx0 = 1.0f - wx1;

    const float* fb = features + (size_t)b * HH * WW * CC;

    float acc = 0.0f;
    if (y0 >= 0 && y0 < HH && x0 >= 0 && x0 < WW)             acc += fb[(y0 * WW + x0) * CC + c] * (wy0 * wx0);
    if (y0 >= 0 && y0 < HH && x0 + 1 >= 0 && x0 + 1 < WW)     acc += fb[(y0 * WW + x0 + 1) * CC + c] * (wy0 * wx1);
    if (y0 + 1 >= 0 && y0 + 1 < HH && x0 >= 0 && x0 < WW)     acc += fb[((y0 + 1) * WW + x0) * CC + c] * (wy1 * wx0);
    if (y0 + 1 >= 0 && y0 + 1 < HH && x0 + 1 >= 0 && x0 + 1 < WW)
        acc += fb[((y0 + 1) * WW + x0 + 1) * CC + c] * (wy1 * wx1);

    __nv_bfloat16 h = __float2bfloat16(acc);
    __nv_bfloat16 l = __float2bfloat16(acc - __bfloat162float(h));
    out_hi[p * CC + c] = h;
    out_lo[p * CC + c] = l;
}

// ---------------------------------------------------------------------------
// Kernel 2: weight transpose + hi/lo bf16 split.
// src w: [K][512] fp32 (K = 3*CIN), dst wt: [512][K] bf16 hi/lo (k-contiguous)
// ---------------------------------------------------------------------------
__global__ void wt_transpose(const float* __restrict__ w,
                             __nv_bfloat16* __restrict__ hi,
                             __nv_bfloat16* __restrict__ lo,
                             int K)
{
    __shared__ float t[32][33];
    const int k0 = blockIdx.x * 32, n0 = blockIdx.y * 32;
    for (int i = threadIdx.y; i < 32; i += 8)
        t[i][threadIdx.x] = w[(size_t)(k0 + i) * HID + n0 + threadIdx.x];
    __syncthreads();
    for (int i = threadIdx.y; i < 32; i += 8) {
        float v = t[threadIdx.x][i];
        __nv_bfloat16 h = __float2bfloat16(v);
        __nv_bfloat16 l = __float2bfloat16(v - __bfloat162float(h));
        size_t o = (size_t)(n0 + i) * K + k0 + threadIdx.x;
        hi[o] = h;
        lo[o] = l;
    }
}

// ---------------------------------------------------------------------------
// Kernel 3: dilated Conv1D as bf16x2 mma.sync GEMM.
//   D[128x128] fp32 per CTA. 8 warps as 2(M) x 4(N), warp tile 64x32.
//   3 MMAs per frag pair (hh, hl, lh) for fp32-grade accuracy.
// grid (MTOT/128, HID/128), 256 threads.
// ---------------------------------------------------------------------------
template <int CIN>
__global__ __launch_bounds__(256, 1)
void conv_mma(const __nv_bfloat16* __restrict__ a_hi,  // [MTOT][CIN]
              const __nv_bfloat16* __restrict__ a_lo,
              const __nv_bfloat16* __restrict__ wt_hi, // [512][3*CIN]
              const __nv_bfloat16* __restrict__ wt_lo,
              const float* __restrict__ bias,          // [512]
              __nv_bfloat16* __restrict__ o_hi,        // [MTOT][512]
              __nv_bfloat16* __restrict__ o_lo,
              int rate)
{
    constexpr int K  = 3 * CIN;
    constexpr int NT = K / 32;        // 32-wide K chunks
    extern __shared__ char smem[];
    const uint32_t sb = smem_u32(smem);

    const int tid  = threadIdx.x;
    const int lane = tid & 31;
    const int warp = tid >> 5;
    const int wm   = warp >> 2;       // 0..1 -> M offset 64*wm
    const int wn   = warp & 3;        // 0..3 -> N offset 32*wn
    const int m0   = blockIdx.x * 128;
    const int co0  = blockIdx.y * 128;
    const int bbase = (m0 >> 10) * NN;

    // preload 128 biases
    if (tid < 128) ((float*)(smem + OFF_BIAS))[tid] = bias[co0 + tid];

    // ---- chunk reg loader / smem storer ----
    auto load_chunk_regs = [&](int c, uint4* v) {
        const int kk0 = c * 32;
        const int tap = kk0 / CIN;
        const int ci0 = kk0 & (CIN - 1);
#pragma unroll
        for (int it = 0; it < 2; ++it) {
            int idx = tid + it * 256;
            int row = idx >> 2, seg = idx & 3;
            int n  = (m0 + row) & (NN - 1);
            int np = n + (tap - 1) * rate;
            uint4 vh = make_uint4(0, 0, 0, 0), vl = make_uint4(0, 0, 0, 0);
            if ((unsigned)np < (unsigned)NN) {
                size_t g = (size_t)(bbase + np) * CIN + ci0 + seg * 8;
                vh = *(const uint4*)(a_hi + g);
                vl = *(const uint4*)(a_lo + g);
            }
            v[it * 2 + 0] = vh;
            v[it * 2 + 1] = vl;
        }
#pragma unroll
        for (int it = 0; it < 2; ++it) {
            int idx = tid + it * 256;
            int row = idx >> 2, seg = idx & 3;
            size_t g = (size_t)(co0 + row) * K + kk0 + seg * 8;
            v[4 + it * 2 + 0] = *(const uint4*)(wt_hi + g);
            v[4 + it * 2 + 1] = *(const uint4*)(wt_lo + g);
        }
    };
    auto store_chunk = [&](int bf, const uint4* v) {
        char* base = smem + bf * BUFB;
#pragma unroll
        for (int it = 0; it < 2; ++it) {
            int idx = tid + it * 256;
            int row = idx >> 2, seg = idx & 3;
            int off = row * ROWB + seg * 16;
            *(uint4*)(base + off)          = v[it * 2 + 0];
            *(uint4*)(base + OFF_AL + off) = v[it * 2 + 1];
            *(uint4*)(base + OFF_BH + off) = v[4 + it * 2 + 0];
            *(uint4*)(base + OFF_BL + off) = v[4 + it * 2 + 1];
        }
    };

    float acc[4][4][4];
#pragma unroll
    for (int i = 0; i < 4; ++i)
#pragma unroll
        for (int j = 0; j < 4; ++j)
#pragma unroll
            for (int q = 0; q < 4; ++q) acc[i][j][q] = 0.0f;

    // prologue
    {
        uint4 v[8];
        load_chunk_regs(0, v);
        store_chunk(0, v);
    }
    __syncthreads();

    for (int c = 0; c < NT; ++c) {
        uint4 v[8];
        if (c + 1 < NT) load_chunk_regs(c + 1, v);

        const uint32_t sA = sb + (uint32_t)((c & 1) * BUFB);
        const uint32_t sB = sA + OFF_BH;

#pragma unroll
        for (int ks = 0; ks < 2; ++ks) {
            const uint32_t kb = (uint32_t)(ks * 32 + (lane >> 4) * 16); // byte off along k
            uint32_t aH[4][4], aL[4][4], bH[4][2], bL[4][2];
#pragma unroll
            for (int mf = 0; mf < 4; ++mf) {
                uint32_t r = sA + (uint32_t)((wm * 64 + mf * 16 + (lane & 15)) * ROWB) + kb;
                LDMX4(aH[mf][0], aH[mf][1], aH[mf][2], aH[mf][3], r);
                LDMX4(aL[mf][0], aL[mf][1], aL[mf][2], aL[mf][3], r + OFF_AL);
            }
#pragma unroll
            for (int np = 0; np < 2; ++np) {
                uint32_t r = sB + (uint32_t)((wn * 32 + np * 16 + (lane & 15)) * ROWB) + kb;
                uint32_t t0, t1, t2, t3;
                LDMX4(t0, t1, t2, t3, r);
                bH[np * 2 + 0][0] = t0; bH[np * 2 + 0][1] = t2;
                bH[np * 2 + 1][0] = t1; bH[np * 2 + 1][1] = t3;
                LDMX4(t0, t1, t2, t3, r + (OFF_BL - OFF_BH));
                bL[np * 2 + 0][0] = t0; bL[np * 2 + 0][1] = t2;
                bL[np * 2 + 1][0] = t1; bL[np * 2 + 1][1] = t3;
            }
#pragma unroll
            for (int mf = 0; mf < 4; ++mf)
#pragma unroll
                for (int nf = 0; nf < 4; ++nf) {
                    MMA16816(acc[mf][nf], aH[mf], bH[nf]);
                    MMA16816(acc[mf][nf], aH[mf], bL[nf]);
                    MMA16816(acc[mf][nf], aL[mf], bH[nf]);
                }
        }

        if (c + 1 < NT) store_chunk((c + 1) & 1, v);
        __syncthreads();
    }

    // ---- epilogue: bias + relu, bf16 hi/lo split, store ----
    const float* bias_s = (const float*)(smem + OFF_BIAS);
#pragma unroll
    for (int mf = 0; mf < 4; ++mf) {
        const int r0 = m0 + wm * 64 + mf * 16 + (lane >> 2);
#pragma unroll
        for (int nf = 0; nf < 4; ++nf) {
            const int colr = wn * 32 + nf * 8 + (lane & 3) * 2;
            const float b0 = bias_s[colr], b1 = bias_s[colr + 1];

            float v0 = fmaxf(acc[mf][nf][0] + b0, 0.0f);
            float v1 = fmaxf(acc[mf][nf][1] + b1, 0.0f);
            float v2 = fmaxf(acc[mf][nf][2] + b0, 0.0f);
            float v3 = fmaxf(acc[mf][nf][3] + b1, 0.0f);

            __nv_bfloat16 h0 = __float2bfloat16(v0), h1 = __float2bfloat16(v1);
            __nv_bfloat16 h2 = __float2bfloat16(v2), h3 = __float2bfloat16(v3);
            __nv_bfloat16 l0 = __float2bfloat16(v0 - __bfloat162float(h0));
            __nv_bfloat16 l1 = __float2bfloat16(v1 - __bfloat162float(h1));
            __nv_bfloat16 l2 = __float2bfloat16(v2 - __bfloat162float(h2));
            __nv_bfloat16 l3 = __float2bfloat16(v3 - __bfloat162float(h3));

            uint32_t hp01 = ((uint32_t)__bfloat16_as_ushort(h1) << 16) | __bfloat16_as_ushort(h0);
            uint32_t lp01 = ((uint32_t)__bfloat16_as_ushort(l1) << 16) | __bfloat16_as_ushort(l0);
            uint32_t hp23 = ((uint32_t)__bfloat16_as_ushort(h3) << 16) | __bfloat16_as_ushort(h2);
            uint32_t lp23 = ((uint32_t)__bfloat16_as_ushort(l3) << 16) | __bfloat16_as_ushort(l2);

            size_t o0 = (size_t)r0 * HID + co0 + colr;
            size_t o1 = (size_t)(r0 + 8) * HID + co0 + colr;
            *(uint32_t*)(o_hi + o0) = hp01;
            *(uint32_t*)(o_lo + o0) = lp01;
            *(uint32_t*)(o_hi + o1) = hp23;
            *(uint32_t*)(o_lo + o1) = lp23;
        }
    }
}

// ---------------------------------------------------------------------------
// Kernel 4: offset head (1x1 conv, no bias) + add vertices. One warp per point.
// ---------------------------------------------------------------------------
__global__ __launch_bounds__(256)
void offset_head(const __nv_bfloat16* __restrict__ h_hi,
                 const __nv_bfloat16* __restrict__ h_lo,
                 const float* __restrict__ w_off,   // [512, 2]
                 const float* __restrict__ vertices,
                 float* __restrict__ out)
{
    const int warp = threadIdx.x >> 5;
    const int lane = threadIdx.x & 31;
    const int p = blockIdx.x * 8 + warp;
    if (p >= MTOT) return;

    const __nv_bfloat16* hh = h_hi + (size_t)p * HID;
    const __nv_bfloat16* hl = h_lo + (size_t)p * HID;
    float s0 = 0.f, s1 = 0.f;
#pragma unroll
    for (int ci = lane; ci < HID; ci += 32) {
        float v = __bfloat162float(hh[ci]) + __bfloat162float(hl[ci]);
        s0 = fmaf(v, w_off[2 * ci + 0], s0);
        s1 = fmaf(v, w_off[2 * ci + 1], s1);
    }
#pragma unroll
    for (int o = 16; o > 0; o >>= 1) {
        s0 += __shfl_xor_sync(0xFFFFFFFFu, s0, o);
        s1 += __shfl_xor_sync(0xFFFFFFFFu, s1, o);
    }
    if (lane == 0) {
        out[2 * p + 0] = vertices[2 * p + 0] + s0;
        out[2 * p + 1] = vertices[2 * p + 1] + s1;
    }
}

// ---------------------------------------------------------------------------
// Launch. Inputs: vertices, features, w0,b0,...,w5,b5, w_off
// ---------------------------------------------------------------------------
extern "C" void kernel_launch(void* const* d_in, const int* in_sizes, int n_in,
                              void* d_out, int out_size)
{
    const float* vertices = (const float*)d_in[0];
    const float* features = (const float*)d_in[1];
    const float* w[6];
    const float* b[6];
    for (int i = 0; i < 6; ++i) {
        w[i] = (const float*)d_in[2 + 2 * i];
        b[i] = (const float*)d_in[3 + 2 * i];
    }
    const float* w_off = (const float*)d_in[14];
    float* out = (float*)d_out;

    __nv_bfloat16 *h0h, *h0l, *ah, *al, *bh, *bl, *wth, *wtl;
    cudaGetSymbolAddress((void**)&h0h, g_h0_hi);
    cudaGetSymbolAddress((void**)&h0l, g_h0_lo);
    cudaGetSymbolAddress((void**)&ah,  g_a_hi);
    cudaGetSymbolAddress((void**)&al,  g_a_lo);
    cudaGetSymbolAddress((void**)&bh,  g_b_hi);
    cudaGetSymbolAddress((void**)&bl,  g_b_lo);
    cudaGetSymbolAddress((void**)&wth, g_wt_hi);
    cudaGetSymbolAddress((void**)&wtl, g_wt_lo);

    cudaFuncSetAttribute(conv_mma<256>, cudaFuncAttributeMaxDynamicSharedMemorySize, SMEM_TOTAL);
    cudaFuncSetAttribute(conv_mma<512>, cudaFuncAttributeMaxDynamicSharedMemorySize, SMEM_TOTAL);

    // weight transposes + hi/lo split
    size_t off[6];
    off[0] = 0;
    for (int i = 1; i < 6; ++i) off[i] = WT0_SZ + (size_t)(i - 1) * WTI_SZ;
    wt_transpose<<<dim3(768 / 32, 16), dim3(32, 8)>>>(w[0], wth + off[0], wtl + off[0], 768);
    for (int i = 1; i < 6; ++i)
        wt_transpose<<<dim3(1536 / 32, 16), dim3(32, 8)>>>(w[i], wth + off[i], wtl + off[i], 1536);

    // bilinear sampling -> h0 (hi/lo)
    sample_kernel<<<MTOT, 256>>>(vertices, features, h0h, h0l);

    const dim3 grid(MTOT / 128, HID / 128);

    // conv stack, rates (1,3,9,9,3,1)
    conv_mma<256><<<grid, 256, SMEM_TOTAL>>>(h0h, h0l, wth + off[0], wtl + off[0], b[0], ah, al, 1);
    conv_mma<512><<<grid, 256, SMEM_TOTAL>>>(ah, al, wth + off[1], wtl + off[1], b[1], bh, bl, 3);
    conv_mma<512><<<grid, 256, SMEM_TOTAL>>>(bh, bl, wth + off[2], wtl + off[2], b[2], ah, al, 9);
    conv_mma<512><<<grid, 256, SMEM_TOTAL>>>(ah, al, wth + off[3], wtl + off[3], b[3], bh, bl, 9);
    conv_mma<512><<<grid, 256, SMEM_TOTAL>>>(bh, bl, wth + off[4], wtl + off[4], b[4], ah, al, 3);
    conv_mma<512><<<grid, 256, SMEM_TOTAL>>>(ah, al, wth + off[5], wtl + off[5], b[5], bh, bl, 1);

    // offset head + residual add
    offset_head<<<MTOT / 8, 256>>>(bh, bl, w_off, vertices, out);
}